// round 1
// baseline (speedup 1.0000x reference)
#include <cuda_runtime.h>

// BAM spatial self-attention, fused flash-style. fp32 throughout.
// B=8, C=256, N=4096 (64x64), CK=32.

#define BATCH 8
#define NPOS 4096
#define CDIM 256
#define CKDIM 32

// Scratch: projected Q/K/V, position-major for coalesced attention tiles.
__device__ float g_q[BATCH * NPOS * CKDIM];          // [b][n][32]
__device__ float g_k[BATCH * NPOS * CKDIM];          // [b][n][32]
__device__ float g_v[BATCH * NPOS * CDIM];           // [b][n][256]

// ---------------- packed f32x2 helpers (Blackwell FFMA2) ----------------
__device__ __forceinline__ unsigned long long pack2(float lo, float hi) {
    unsigned long long r;
    asm("mov.b64 %0, {%1, %2};" : "=l"(r) : "f"(lo), "f"(hi));
    return r;
}
__device__ __forceinline__ void unpack2(unsigned long long v, float& lo, float& hi) {
    asm("mov.b64 {%0, %1}, %2;" : "=f"(lo), "=f"(hi) : "l"(v));
}
__device__ __forceinline__ unsigned long long fma2(unsigned long long a,
                                                   unsigned long long b,
                                                   unsigned long long c) {
    unsigned long long d;
    asm("fma.rn.f32x2 %0, %1, %2, %3;" : "=l"(d) : "l"(a), "l"(b), "l"(c));
    return d;
}
__device__ __forceinline__ unsigned long long mul2(unsigned long long a,
                                                   unsigned long long b) {
    unsigned long long d;
    asm("mul.rn.f32x2 %0, %1, %2;" : "=l"(d) : "l"(a), "l"(b));
    return d;
}

// ---------------- Kernel A: Q/K/V projections ----------------
// Conceptual W = concat(Wq[32], Wk[32], Wv[256]) -> 320 output channels.
// Grid: (N/64 n-tiles, 5 o-tiles of 64, B). Block 256 = 16x16, 4x4 reg tiles.
__global__ __launch_bounds__(256) void proj_kernel(
    const float* __restrict__ x,
    const float* __restrict__ Wq, const float* __restrict__ bq,
    const float* __restrict__ Wk, const float* __restrict__ bk,
    const float* __restrict__ Wv, const float* __restrict__ bv)
{
    __shared__ float xs[16][64];   // [c-chunk][n]
    __shared__ float ws[16][64];   // [c-chunk][o]

    const int b  = blockIdx.z;
    const int n0 = blockIdx.x * 64;
    const int ob = blockIdx.y * 64;
    const int tid = threadIdx.x;
    const int tx = tid & 15;       // n-group
    const int ty = tid >> 4;       // o-group

    float acc[4][4];
#pragma unroll
    for (int i = 0; i < 4; i++)
#pragma unroll
        for (int j = 0; j < 4; j++) acc[i][j] = 0.0f;

    const float* xb = x + (size_t)b * CDIM * NPOS;

    for (int c0 = 0; c0 < CDIM; c0 += 16) {
        __syncthreads();
        // xs: 1024 floats, one float4 per thread, coalesced over n
        {
            const int cc = tid >> 4;
            const int nn = (tid & 15) * 4;
            *(float4*)&xs[cc][nn] =
                *(const float4*)(xb + (size_t)(c0 + cc) * NPOS + n0 + nn);
        }
        // ws[cc][o]: 1024 floats
        for (int e = tid; e < 1024; e += 256) {
            const int o  = e >> 4;
            const int cc = e & 15;
            const int og = ob + o;
            const float* wrow;
            if (og < 32)       wrow = Wq + og * CDIM;
            else if (og < 64)  wrow = Wk + (og - 32) * CDIM;
            else               wrow = Wv + (og - 64) * CDIM;
            ws[cc][o] = wrow[c0 + cc];
        }
        __syncthreads();
#pragma unroll
        for (int cc = 0; cc < 16; cc++) {
            const float4 wv = *(const float4*)&ws[cc][ty * 4];
            const float4 xv = *(const float4*)&xs[cc][tx * 4];
            const float wa[4] = {wv.x, wv.y, wv.z, wv.w};
            const float xa[4] = {xv.x, xv.y, xv.z, xv.w};
#pragma unroll
            for (int i = 0; i < 4; i++)
#pragma unroll
                for (int j = 0; j < 4; j++)
                    acc[i][j] = fmaf(wa[i], xa[j], acc[i][j]);
        }
    }

    // Epilogue: bias + store to [b][n][o] scratch (float4 over o)
    const int og0 = ob + ty * 4;
    float bias[4];
#pragma unroll
    for (int i = 0; i < 4; i++) {
        const int og = og0 + i;
        bias[i] = (og < 32) ? bq[og] : (og < 64 ? bk[og - 32] : bv[og - 64]);
    }
#pragma unroll
    for (int j = 0; j < 4; j++) {
        const size_t nidx = ((size_t)b << 12) + n0 + tx * 4 + j;
        float4 v;
        v.x = acc[0][j] + bias[0];
        v.y = acc[1][j] + bias[1];
        v.z = acc[2][j] + bias[2];
        v.w = acc[3][j] + bias[3];
        if (og0 < 32)
            *(float4*)&g_q[nidx * CKDIM + og0] = v;
        else if (og0 < 64)
            *(float4*)&g_k[nidx * CKDIM + (og0 - 32)] = v;
        else
            *(float4*)&g_v[nidx * CDIM + (og0 - 64)] = v;
    }
}

// ---------------- Kernel B: fused flash attention + residual ----------------
// CTA = (64-query tile, batch). 256 threads = 16(ty: m-groups) x 16(tx).
// Online softmax over 64 key tiles of 64 keys. O accumulated as f32x2 pairs.
//
// Dynamic smem layout (floats):
//   qs[32][64]  @0      : q, channel-major
//   ks[32][64]  @2048   : key tile, channel-major
//   ps[64][68]  @4096   : P tile, row m, padded stride 68 (16B-aligned rows)
//   vs[64][256] @8448   : V tile (also reused as O staging [256][64])
#define SM_QS 0
#define SM_KS 2048
#define SM_PS 4096
#define SM_VS 8448
#define SMEM_FLOATS (8448 + 64 * 256)

extern "C" __global__ void __launch_bounds__(256, 2) attn_kernel(
    const float* __restrict__ x,
    const float* __restrict__ gamma,
    float* __restrict__ out)
{
    extern __shared__ float sm[];
    float* qs = sm + SM_QS;
    float* ks = sm + SM_KS;
    float* ps = sm + SM_PS;
    float* vs = sm + SM_VS;

    const int b  = blockIdx.y;
    const int m0 = blockIdx.x * 64;
    const int tid = threadIdx.x;
    const int tx = tid & 15;
    const int ty = tid >> 4;

    // Load Q tile -> qs[c][m] (coalesced float4 reads, scalar scattered stores)
    {
        const float* qsrc = g_q + (((size_t)b << 12) + m0) * CKDIM;
        for (int e = tid; e < 512; e += 256) {
            const int m  = e >> 3;
            const int c4 = (e & 7) * 4;
            const float4 qv = *(const float4*)(qsrc + (size_t)m * CKDIM + c4);
            qs[(c4 + 0) * 64 + m] = qv.x;
            qs[(c4 + 1) * 64 + m] = qv.y;
            qs[(c4 + 2) * 64 + m] = qv.z;
            qs[(c4 + 3) * 64 + m] = qv.w;
        }
    }

    float rm[4], rs[4];
    unsigned long long a2[4][8];
#pragma unroll
    for (int i = 0; i < 4; i++) {
        rm[i] = -1e30f;
        rs[i] = 0.0f;
#pragma unroll
        for (int j = 0; j < 8; j++) a2[i][j] = pack2(0.0f, 0.0f);
    }

    const float* KTb = g_k + ((size_t)b << 12) * CKDIM;
    const float* VTb = g_v + ((size_t)b << 12) * CDIM;

    for (int kt = 0; kt < 64; kt++) {
        __syncthreads();  // previous PV done; safe to overwrite ks/vs (and qs ready on iter 0)

        // K tile -> ks[c][n]
        {
            const float* ksrc = KTb + (size_t)(kt * 64) * CKDIM;
            for (int e = tid; e < 512; e += 256) {
                const int n  = e >> 3;
                const int c4 = (e & 7) * 4;
                const float4 kv = *(const float4*)(ksrc + (size_t)n * CKDIM + c4);
                ks[(c4 + 0) * 64 + n] = kv.x;
                ks[(c4 + 1) * 64 + n] = kv.y;
                ks[(c4 + 2) * 64 + n] = kv.z;
                ks[(c4 + 3) * 64 + n] = kv.w;
            }
        }
        // V tile -> vs[n][c] (direct float4 copy)
        {
            const float* vsrc = VTb + (size_t)(kt * 64) * CDIM;
            for (int e = tid; e < 4096; e += 256) {
                const int n  = e >> 6;
                const int c4 = (e & 63) * 4;
                *(float4*)&vs[n * 256 + c4] =
                    *(const float4*)(vsrc + (size_t)n * CDIM + c4);
            }
        }
        __syncthreads();

        // S = Q^T K : 4x4 per thread
        float s[4][4];
#pragma unroll
        for (int i = 0; i < 4; i++)
#pragma unroll
            for (int j = 0; j < 4; j++) s[i][j] = 0.0f;
#pragma unroll
        for (int c = 0; c < 32; c++) {
            const float4 qv = *(const float4*)&qs[c * 64 + ty * 4];
            const float4 kv = *(const float4*)&ks[c * 64 + tx * 4];
            const float qa[4] = {qv.x, qv.y, qv.z, qv.w};
            const float ka[4] = {kv.x, kv.y, kv.z, kv.w};
#pragma unroll
            for (int i = 0; i < 4; i++)
#pragma unroll
                for (int j = 0; j < 4; j++)
                    s[i][j] = fmaf(qa[i], ka[j], s[i][j]);
        }

        // Online softmax per m-row (half-warp: 16 lanes with same ty own a row)
#pragma unroll
        for (int i = 0; i < 4; i++) {
            float tmax = fmaxf(fmaxf(s[i][0], s[i][1]), fmaxf(s[i][2], s[i][3]));
#pragma unroll
            for (int w = 1; w < 16; w <<= 1)
                tmax = fmaxf(tmax, __shfl_xor_sync(0xffffffffu, tmax, w));
            const float nm = fmaxf(rm[i], tmax);
            const float scale = __expf(rm[i] - nm);
            float4 p;
            p.x = __expf(s[i][0] - nm);
            p.y = __expf(s[i][1] - nm);
            p.z = __expf(s[i][2] - nm);
            p.w = __expf(s[i][3] - nm);
            float tsum = (p.x + p.y) + (p.z + p.w);
#pragma unroll
            for (int w = 1; w < 16; w <<= 1)
                tsum += __shfl_xor_sync(0xffffffffu, tsum, w);
            rs[i] = rs[i] * scale + tsum;
            rm[i] = nm;
            *(float4*)&ps[(ty * 4 + i) * 68 + tx * 4] = p;
            const unsigned long long sc2 = pack2(scale, scale);
#pragma unroll
            for (int j = 0; j < 8; j++) a2[i][j] = mul2(a2[i][j], sc2);
        }
        __syncthreads();  // ps visible to all

        // PV: O[m][c] += sum_n P[m][n] * V[n][c]
        // Thread channels: c = blk*64 + tx*4 + {0..3}, blk 0..3
#pragma unroll 2
        for (int n = 0; n < 64; n++) {
            const float4 v0 = *(const float4*)&vs[n * 256 +   0 + tx * 4];
            const float4 v1 = *(const float4*)&vs[n * 256 +  64 + tx * 4];
            const float4 v2 = *(const float4*)&vs[n * 256 + 128 + tx * 4];
            const float4 v3 = *(const float4*)&vs[n * 256 + 192 + tx * 4];
            unsigned long long vv[8];
            vv[0] = pack2(v0.x, v0.y); vv[1] = pack2(v0.z, v0.w);
            vv[2] = pack2(v1.x, v1.y); vv[3] = pack2(v1.z, v1.w);
            vv[4] = pack2(v2.x, v2.y); vv[5] = pack2(v2.z, v2.w);
            vv[6] = pack2(v3.x, v3.y); vv[7] = pack2(v3.z, v3.w);
#pragma unroll
            for (int i = 0; i < 4; i++) {
                const float p = ps[(ty * 4 + i) * 68 + n];
                const unsigned long long pp = pack2(p, p);
#pragma unroll
                for (int j = 0; j < 8; j++) a2[i][j] = fma2(pp, vv[j], a2[i][j]);
            }
        }
    }

    // Stage normalized O into vs as [c][m]
    __syncthreads();
#pragma unroll
    for (int i = 0; i < 4; i++) {
        const float inv = 1.0f / rs[i];
        const int m = ty * 4 + i;
#pragma unroll
        for (int j = 0; j < 8; j++) {
            float lo, hi;
            unpack2(a2[i][j], lo, hi);
            const int c = (j >> 1) * 64 + tx * 4 + (j & 1) * 2;
            vs[(c + 0) * 64 + m] = lo * inv;
            vs[(c + 1) * 64 + m] = hi * inv;
        }
    }
    __syncthreads();

    // y = gamma*O + x, coalesced over m
    const float g = gamma[0];
    const float* xb = x   + (size_t)b * CDIM * NPOS + m0;
    float*       ob = out + (size_t)b * CDIM * NPOS + m0;
    for (int e = tid; e < 16384; e += 256) {
        const int c = e >> 6;
        const int m = e & 63;
        const size_t off = (size_t)c * NPOS + m;
        ob[off] = fmaf(g, vs[c * 64 + m], xb[off]);
    }
}

// ---------------- launch ----------------
extern "C" void kernel_launch(void* const* d_in, const int* in_sizes, int n_in,
                              void* d_out, int out_size)
{
    const float* x     = (const float*)d_in[0];
    const float* Wq    = (const float*)d_in[1];
    const float* bq    = (const float*)d_in[2];
    const float* Wk    = (const float*)d_in[3];
    const float* bk    = (const float*)d_in[4];
    const float* Wv    = (const float*)d_in[5];
    const float* bv    = (const float*)d_in[6];
    const float* gamma = (const float*)d_in[7];
    float* out = (float*)d_out;

    proj_kernel<<<dim3(NPOS / 64, 5, BATCH), 256>>>(x, Wq, bq, Wk, bk, Wv, bv);

    const int smem_bytes = SMEM_FLOATS * sizeof(float);
    cudaFuncSetAttribute(attn_kernel,
                         cudaFuncAttributeMaxDynamicSharedMemorySize, smem_bytes);
    attn_kernel<<<dim3(NPOS / 64, BATCH), 256, smem_bytes>>>(x, gamma, out);
}